// round 1
// baseline (speedup 1.0000x reference)
#include <cuda_runtime.h>

// SwinV2 shifted-window attention, B=16, H=W=64, C=256, heads=8, hd=32,
// window 8x8, shift 4x4  ->  1024 windows x 64 tokens.
//
// Round 0: full fp32 SIMT baseline (correctness + profile). Tensor cores next.

#define NWIN   1024          // B * 64 windows
#define NTOK   64            // tokens per window
#define CDIM   256
#define NHEAD  8
#define HD     32

// -------- scratch (device globals; no allocation) --------
__device__ float g_q  [NWIN * NHEAD * NTOK * HD];   // normalized q  (64 MB)
__device__ float g_k  [NWIN * NHEAD * NTOK * HD];   // normalized k  (64 MB)
__device__ float g_v  [NWIN * NHEAD * NTOK * HD];   // v             (64 MB)
__device__ float g_ao [NWIN * NTOK * CDIM];         // attn out      (64 MB)
__device__ float g_bias16[NHEAD * 225];             // 16*sigmoid(cpb)
__device__ float g_scale[NHEAD];                    // exp(min(ls, ln100))

// ============================================================
// Kernel 0: continuous-position-bias MLP  (225 entries -> 512 -> 8 heads)
// grid 225 blocks x 512 threads
// ============================================================
__global__ void swin_bias_kernel(const float* __restrict__ ls,
                                 const float* __restrict__ w1,
                                 const float* __restrict__ b1,
                                 const float* __restrict__ w2)
{
    __shared__ float part[16][8];
    const int t   = blockIdx.x;          // 0..224
    const int i   = t / 15;
    const int j   = t % 15;
    const int tid = threadIdx.x;         // 0..511
    const int warp = tid >> 5;
    const int lane = tid & 31;

    float rh = (float)(i - 7) * (8.0f / 7.0f);
    float rw = (float)(j - 7) * (8.0f / 7.0f);
    rh = copysignf(log2f(fabsf(rh) + 1.0f) * (1.0f / 3.0f), rh);
    rw = copysignf(log2f(fabsf(rw) + 1.0f) * (1.0f / 3.0f), rw);

    float hv = fmaxf(0.0f, rh * w1[tid] + rw * w1[512 + tid] + b1[tid]);

    float p[8];
#pragma unroll
    for (int h = 0; h < 8; ++h) p[h] = hv * w2[tid * 8 + h];
#pragma unroll
    for (int off = 16; off; off >>= 1)
#pragma unroll
        for (int h = 0; h < 8; ++h) p[h] += __shfl_xor_sync(0xffffffffu, p[h], off);
    if (lane == 0)
#pragma unroll
        for (int h = 0; h < 8; ++h) part[warp][h] = p[h];
    __syncthreads();

    if (tid < 8) {
        float s = 0.0f;
#pragma unroll
        for (int g = 0; g < 16; ++g) s += part[g][tid];
        g_bias16[tid * 225 + t] = 16.0f / (1.0f + expf(-s));
    }
    if (blockIdx.x == 0 && tid < 8)
        g_scale[tid] = expf(fminf(ls[tid], 4.6051701860f));   // ln(100)
}

// ============================================================
// Kernel 1: shift + window gather + QKV projection + cosine-normalize
// grid 1024 (one window), 256 threads, dyn smem: Xs[64][260] + Wt[16][256]
// thread tile: 8 rows x (2x4) cols.  cols c = jj*128 + lane*4 + q
// ============================================================
#define K1_SMEM ((64 * 260 + 16 * 256) * 4)

__global__ void __launch_bounds__(256, 2)
swin_qkv_kernel(const float* __restrict__ x,
                const float* __restrict__ Wq, const float* __restrict__ bq,
                const float* __restrict__ Wk, const float* __restrict__ bk,
                const float* __restrict__ Wv, const float* __restrict__ bv)
{
    extern __shared__ float sm[];
    float* Xs = sm;                 // [64][260] padded
    float* Wt = sm + 64 * 260;      // [16][256]

    const int w    = blockIdx.x;
    const int b    = w >> 6;
    const int wy   = (w >> 3) & 7;
    const int wx   = w & 7;
    const int tid  = threadIdx.x;
    const int warp = tid >> 5;
    const int lane = tid & 31;

    // gather shifted window: xs[gy][gx] = x[(gy+4)&63][(gx+4)&63]
#pragma unroll
    for (int it = 0; it < 16; ++it) {
        int idx = tid + it * 256;        // float4 index 0..4095
        int n   = idx >> 6;
        int c4  = idx & 63;
        int sy  = ((wy << 3) + (n >> 3) + 4) & 63;
        int sx  = ((wx << 3) + (n & 7) + 4) & 63;
        float4 val = *(const float4*)(x + (((b << 6) | sy) << 14) + (sx << 8) + (c4 << 2));
        *(float4*)(Xs + n * 260 + (c4 << 2)) = val;
    }

    const float* Wm[3] = {Wq, Wk, Wv};
    const float* Bm[3] = {bq, bk, bv};
    float*       Gm[3] = {g_q, g_k, g_v};

#pragma unroll
    for (int m = 0; m < 3; ++m) {
        float acc[8][2][4];
#pragma unroll
        for (int i = 0; i < 8; ++i)
#pragma unroll
            for (int jj = 0; jj < 2; ++jj)
#pragma unroll
                for (int q = 0; q < 4; ++q) acc[i][jj][q] = 0.0f;

        const float* W = Wm[m];
        for (int kc = 0; kc < 16; ++kc) {
            __syncthreads();                       // protect Wt (and Xs on first pass)
#pragma unroll
            for (int it = 0; it < 4; ++it) {
                int idx = tid + it * 256;          // float4 index 0..1023
                int kk  = idx >> 6;
                int c4  = idx & 63;
                *(float4*)(Wt + kk * 256 + (c4 << 2)) =
                    *(const float4*)(W + ((kc * 16 + kk) << 8) + (c4 << 2));
            }
            __syncthreads();
#pragma unroll
            for (int kk = 0; kk < 16; ++kk) {
                float4 b0 = *(float4*)(Wt + kk * 256 + (lane << 2));
                float4 b1 = *(float4*)(Wt + kk * 256 + 128 + (lane << 2));
#pragma unroll
                for (int i = 0; i < 8; ++i) {
                    float a = Xs[(warp * 8 + i) * 260 + kc * 16 + kk];
                    acc[i][0][0] += a * b0.x;  acc[i][0][1] += a * b0.y;
                    acc[i][0][2] += a * b0.z;  acc[i][0][3] += a * b0.w;
                    acc[i][1][0] += a * b1.x;  acc[i][1][1] += a * b1.y;
                    acc[i][1][2] += a * b1.z;  acc[i][1][3] += a * b1.w;
                }
            }
        }

        // bias
        float4 bb0 = *(const float4*)(Bm[m] + (lane << 2));
        float4 bb1 = *(const float4*)(Bm[m] + 128 + (lane << 2));
#pragma unroll
        for (int i = 0; i < 8; ++i) {
            acc[i][0][0] += bb0.x; acc[i][0][1] += bb0.y;
            acc[i][0][2] += bb0.z; acc[i][0][3] += bb0.w;
            acc[i][1][0] += bb1.x; acc[i][1][1] += bb1.y;
            acc[i][1][2] += bb1.z; acc[i][1][3] += bb1.w;
        }

        // cosine normalization for q,k: reduce ssq over 32 head dims
        // (4 local cols x 8 lanes sharing lane>>3)
        if (m < 2) {
#pragma unroll
            for (int i = 0; i < 8; ++i)
#pragma unroll
                for (int jj = 0; jj < 2; ++jj) {
                    float s = acc[i][jj][0] * acc[i][jj][0]
                            + acc[i][jj][1] * acc[i][jj][1]
                            + acc[i][jj][2] * acc[i][jj][2]
                            + acc[i][jj][3] * acc[i][jj][3];
                    s += __shfl_xor_sync(0xffffffffu, s, 1);
                    s += __shfl_xor_sync(0xffffffffu, s, 2);
                    s += __shfl_xor_sync(0xffffffffu, s, 4);
                    float inv = 1.0f / fmaxf(sqrtf(s), 1e-12f);
                    acc[i][jj][0] *= inv; acc[i][jj][1] *= inv;
                    acc[i][jj][2] *= inv; acc[i][jj][3] *= inv;
                }
        }

        // store [win][head][tok][hd]
        float* G = Gm[m];
#pragma unroll
        for (int i = 0; i < 8; ++i) {
            int n = warp * 8 + i;
#pragma unroll
            for (int jj = 0; jj < 2; ++jj) {
                int head = jj * 4 + (lane >> 3);
                int d0   = (lane & 7) << 2;
                *(float4*)(G + ((((w << 3) | head) << 6 | n) << 5) + d0) =
                    make_float4(acc[i][jj][0], acc[i][jj][1], acc[i][jj][2], acc[i][jj][3]);
            }
        }
    }
}

// ============================================================
// Kernel 2: per (window, head) attention.  grid (1024, 8), 64 threads.
// thread = one query row.  logits buffered in padded smem row.
// ============================================================
__global__ void __launch_bounds__(64)
swin_attn_kernel()
{
    __shared__ float ks[NTOK * HD];
    __shared__ float vs[NTOK * HD];
    __shared__ float ps[NTOK * 65];        // padded logit rows
    __shared__ float bs[225];

    const int w   = blockIdx.x;
    const int h   = blockIdx.y;
    const int tid = threadIdx.x;           // query token 0..63
    const int base = ((w << 3) | h) << 11; // *2048

    const float4* k4 = (const float4*)(g_k + base);
    const float4* v4 = (const float4*)(g_v + base);
#pragma unroll
    for (int it = 0; it < 8; ++it) {
        int idx = tid + it * 64;
        ((float4*)ks)[idx] = k4[idx];
        ((float4*)vs)[idx] = v4[idx];
    }
    for (int idx = tid; idx < 225; idx += 64) bs[idx] = g_bias16[h * 225 + idx];

    float qr[32];
    const float4* q4 = (const float4*)(g_q + base + tid * HD);
#pragma unroll
    for (int it = 0; it < 8; ++it) ((float4*)qr)[it] = q4[it];
    __syncthreads();

    const float sc = g_scale[h];
    const int wy = (w >> 3) & 7, wx = w & 7;
    const int ty = tid >> 3,     tx = tid & 7;
    const bool mh = (wy == 7), mw = (wx == 7);
    const bool tyl = (ty < 4), txl = (tx < 4);

    float mx = -1e30f;
    for (int m = 0; m < 64; ++m) {
        float dot = 0.0f;
#pragma unroll
        for (int d = 0; d < 32; ++d) dot += qr[d] * ks[m * 32 + d];
        int my = m >> 3, mxc = m & 7;
        float l = dot * sc + bs[(ty - my + 7) * 15 + (tx - mxc + 7)];
        if (mh && (tyl != (my < 4)))  l -= 100.0f;
        if (mw && (txl != (mxc < 4))) l -= 100.0f;
        ps[tid * 65 + m] = l;
        mx = fmaxf(mx, l);
    }

    float sum = 0.0f;
    for (int m = 0; m < 64; ++m) {
        float e = __expf(ps[tid * 65 + m] - mx);
        ps[tid * 65 + m] = e;
        sum += e;
    }
    const float inv = 1.0f / sum;

    float o[32];
#pragma unroll
    for (int d = 0; d < 32; ++d) o[d] = 0.0f;
    for (int m = 0; m < 64; ++m) {
        float p = ps[tid * 65 + m];
#pragma unroll
        for (int d = 0; d < 32; ++d) o[d] += p * vs[m * 32 + d];
    }

    float* dst = g_ao + ((w << 6) | tid) * CDIM + h * HD;
#pragma unroll
    for (int it = 0; it < 8; ++it)
        ((float4*)dst)[it] = make_float4(o[it * 4] * inv, o[it * 4 + 1] * inv,
                                         o[it * 4 + 2] * inv, o[it * 4 + 3] * inv);
}

// ============================================================
// Kernel 3: output projection + inverse window partition + inverse roll
// grid 1024, 256 threads, same GEMM structure as K1.
// ============================================================
__global__ void __launch_bounds__(256, 2)
swin_proj_kernel(const float* __restrict__ Wo, const float* __restrict__ bo,
                 float* __restrict__ out)
{
    extern __shared__ float sm[];
    float* Xs = sm;
    float* Wt = sm + 64 * 260;

    const int w    = blockIdx.x;
    const int b    = w >> 6;
    const int wy   = (w >> 3) & 7;
    const int wx   = w & 7;
    const int tid  = threadIdx.x;
    const int warp = tid >> 5;
    const int lane = tid & 31;

#pragma unroll
    for (int it = 0; it < 16; ++it) {
        int idx = tid + it * 256;
        int n   = idx >> 6;
        int c4  = idx & 63;
        float4 val = *(const float4*)(g_ao + (w << 14) + (n << 8) + (c4 << 2));
        *(float4*)(Xs + n * 260 + (c4 << 2)) = val;
    }

    float acc[8][2][4];
#pragma unroll
    for (int i = 0; i < 8; ++i)
#pragma unroll
        for (int jj = 0; jj < 2; ++jj)
#pragma unroll
            for (int q = 0; q < 4; ++q) acc[i][jj][q] = 0.0f;

    for (int kc = 0; kc < 16; ++kc) {
        __syncthreads();
#pragma unroll
        for (int it = 0; it < 4; ++it) {
            int idx = tid + it * 256;
            int kk  = idx >> 6;
            int c4  = idx & 63;
            *(float4*)(Wt + kk * 256 + (c4 << 2)) =
                *(const float4*)(Wo + ((kc * 16 + kk) << 8) + (c4 << 2));
        }
        __syncthreads();
#pragma unroll
        for (int kk = 0; kk < 16; ++kk) {
            float4 b0 = *(float4*)(Wt + kk * 256 + (lane << 2));
            float4 b1 = *(float4*)(Wt + kk * 256 + 128 + (lane << 2));
#pragma unroll
            for (int i = 0; i < 8; ++i) {
                float a = Xs[(warp * 8 + i) * 260 + kc * 16 + kk];
                acc[i][0][0] += a * b0.x;  acc[i][0][1] += a * b0.y;
                acc[i][0][2] += a * b0.z;  acc[i][0][3] += a * b0.w;
                acc[i][1][0] += a * b1.x;  acc[i][1][1] += a * b1.y;
                acc[i][1][2] += a * b1.z;  acc[i][1][3] += a * b1.w;
            }
        }
    }

    float4 bb0 = *(const float4*)(bo + (lane << 2));
    float4 bb1 = *(const float4*)(bo + 128 + (lane << 2));
#pragma unroll
    for (int i = 0; i < 8; ++i) {
        int n  = warp * 8 + i;
        int ty = n >> 3, tx = n & 7;
        int y  = ((wy << 3) + ty + 4) & 63;       // inverse roll (+shift)
        int xc = ((wx << 3) + tx + 4) & 63;
        float* dst = out + (((b << 6) | y) << 14) + (xc << 8);
        *(float4*)(dst + (lane << 2)) =
            make_float4(acc[i][0][0] + bb0.x, acc[i][0][1] + bb0.y,
                        acc[i][0][2] + bb0.z, acc[i][0][3] + bb0.w);
        *(float4*)(dst + 128 + (lane << 2)) =
            make_float4(acc[i][1][0] + bb1.x, acc[i][1][1] + bb1.y,
                        acc[i][1][2] + bb1.z, acc[i][1][3] + bb1.w);
    }
}

// ============================================================
extern "C" void kernel_launch(void* const* d_in, const int* in_sizes, int n_in,
                              void* d_out, int out_size)
{
    const float* x  = (const float*)d_in[0];
    const float* Wq = (const float*)d_in[1];
    const float* bq = (const float*)d_in[2];
    const float* Wk = (const float*)d_in[3];
    const float* bk = (const float*)d_in[4];
    const float* Wv = (const float*)d_in[5];
    const float* bv = (const float*)d_in[6];
    const float* Wo = (const float*)d_in[7];
    const float* bo = (const float*)d_in[8];
    const float* ls = (const float*)d_in[9];
    const float* w1 = (const float*)d_in[10];
    const float* b1 = (const float*)d_in[11];
    const float* w2 = (const float*)d_in[12];
    float* out = (float*)d_out;

    cudaFuncSetAttribute(swin_qkv_kernel,
                         cudaFuncAttributeMaxDynamicSharedMemorySize, K1_SMEM);
    cudaFuncSetAttribute(swin_proj_kernel,
                         cudaFuncAttributeMaxDynamicSharedMemorySize, K1_SMEM);

    swin_bias_kernel<<<225, 512>>>(ls, w1, b1, w2);
    swin_qkv_kernel<<<NWIN, 256, K1_SMEM>>>(x, Wq, bq, Wk, bk, Wv, bv);
    swin_attn_kernel<<<dim3(NWIN, NHEAD), 64>>>();
    swin_proj_kernel<<<NWIN, 256, K1_SMEM>>>(Wo, bo, out);
}

// round 2
// speedup vs baseline: 1.9877x; 1.9877x over previous
#include <cuda_runtime.h>

// SwinV2 shifted-window attention, B=16, H=W=64, C=256, heads=8, hd=32,
// window 8x8, shift 4x4  ->  1024 windows x 64 tokens.
//
// Round 1: projection GEMMs (QKV + output proj) moved to tensor cores via
// mma.sync.m16n8k8 tf32 (fp32 accumulate). Attention stays fp32 SIMT.

#define NWIN   1024          // B * 64 windows
#define NTOK   64            // tokens per window
#define CDIM   256
#define NHEAD  8
#define HD     32

// -------- scratch (device globals; no allocation) --------
__device__ float g_q  [NWIN * NHEAD * NTOK * HD];   // normalized q
__device__ float g_k  [NWIN * NHEAD * NTOK * HD];   // normalized k
__device__ float g_v  [NWIN * NHEAD * NTOK * HD];   // v
__device__ float g_ao [NWIN * NTOK * CDIM];         // attn out
__device__ float g_bias16[NHEAD * 225];             // 16*sigmoid(cpb)
__device__ float g_scale[NHEAD];                    // exp(min(ls, ln100))

// -------- tf32 helpers --------
__device__ __forceinline__ unsigned f2tf(float f) {
    unsigned u;
    asm("cvt.rna.tf32.f32 %0, %1;" : "=r"(u) : "f"(f));
    return u;
}
__device__ __forceinline__ void mma8(float* c, const unsigned* a, const unsigned* b) {
    asm volatile("mma.sync.aligned.m16n8k8.row.col.f32.tf32.tf32.f32 "
                 "{%0,%1,%2,%3},{%4,%5,%6,%7},{%8,%9},{%0,%1,%2,%3};"
                 : "+f"(c[0]), "+f"(c[1]), "+f"(c[2]), "+f"(c[3])
                 : "r"(a[0]), "r"(a[1]), "r"(a[2]), "r"(a[3]),
                   "r"(b[0]), "r"(b[1]));
}

#define XS_STRIDE 260        // mod 32 == 4  -> A-fragment LDS conflict-free
#define WT_STRIDE 264        // mod 32 == 8  -> B-fragment LDS conflict-free
#define GEMM_SMEM ((64 * XS_STRIDE + 32 * WT_STRIDE) * 4)   // 100352 B

// ============================================================
// Kernel 0: continuous-position-bias MLP  (225 entries -> 512 -> 8 heads)
// ============================================================
__global__ void swin_bias_kernel(const float* __restrict__ ls,
                                 const float* __restrict__ w1,
                                 const float* __restrict__ b1,
                                 const float* __restrict__ w2)
{
    __shared__ float part[16][8];
    const int t   = blockIdx.x;          // 0..224
    const int i   = t / 15;
    const int j   = t % 15;
    const int tid = threadIdx.x;         // 0..511
    const int warp = tid >> 5;
    const int lane = tid & 31;

    float rh = (float)(i - 7) * (8.0f / 7.0f);
    float rw = (float)(j - 7) * (8.0f / 7.0f);
    rh = copysignf(log2f(fabsf(rh) + 1.0f) * (1.0f / 3.0f), rh);
    rw = copysignf(log2f(fabsf(rw) + 1.0f) * (1.0f / 3.0f), rw);

    float hv = fmaxf(0.0f, rh * w1[tid] + rw * w1[512 + tid] + b1[tid]);

    float p[8];
#pragma unroll
    for (int h = 0; h < 8; ++h) p[h] = hv * w2[tid * 8 + h];
#pragma unroll
    for (int off = 16; off; off >>= 1)
#pragma unroll
        for (int h = 0; h < 8; ++h) p[h] += __shfl_xor_sync(0xffffffffu, p[h], off);
    if (lane == 0)
#pragma unroll
        for (int h = 0; h < 8; ++h) part[warp][h] = p[h];
    __syncthreads();

    if (tid < 8) {
        float s = 0.0f;
#pragma unroll
        for (int g = 0; g < 16; ++g) s += part[g][tid];
        g_bias16[tid * 225 + t] = 16.0f / (1.0f + expf(-s));
    }
    if (blockIdx.x == 0 && tid < 8)
        g_scale[tid] = expf(fminf(ls[tid], 4.6051701860f));   // ln(100)
}

// ============================================================
// Kernel 1: shift+window gather + QKV projection (tf32 MMA) + cos-normalize
// grid 1024 windows, 256 threads (8 warps: 2 M-halves x 4 N-quarters)
// ============================================================
__global__ void __launch_bounds__(256, 2)
swin_qkv_kernel(const float* __restrict__ x,
                const float* __restrict__ Wq, const float* __restrict__ bq,
                const float* __restrict__ Wk, const float* __restrict__ bk,
                const float* __restrict__ Wv, const float* __restrict__ bv)
{
    extern __shared__ unsigned sm[];
    unsigned* Xs = sm;                       // [64][XS_STRIDE] tf32 bits
    unsigned* Wt = sm + 64 * XS_STRIDE;      // [32][WT_STRIDE] tf32 bits

    const int w    = blockIdx.x;
    const int b    = w >> 6;
    const int wy   = (w >> 3) & 7;
    const int wx   = w & 7;
    const int tid  = threadIdx.x;
    const int warp = tid >> 5;
    const int lane = tid & 31;
    const int g    = lane >> 2;              // fragment row group
    const int t    = lane & 3;               // fragment k / col group
    const int mhalf = warp >> 2;             // 0..1 -> rows [mhalf*32, +32)
    const int nq    = warp & 3;              // 0..3 -> cols [nq*64, +64)

    // gather shifted window: xs[n] = x[(wy*8+ty+4)&63][(wx*8+tx+4)&63], tf32-cvt
#pragma unroll
    for (int it = 0; it < 16; ++it) {
        int idx = tid + it * 256;            // float4 index 0..4095
        int n   = idx >> 6;
        int c4  = idx & 63;
        int sy  = ((wy << 3) + (n >> 3) + 4) & 63;
        int sx  = ((wx << 3) + (n & 7) + 4) & 63;
        float4 v = *(const float4*)(x + (((b << 6) | sy) << 14) + (sx << 8) + (c4 << 2));
        uint4 u = make_uint4(f2tf(v.x), f2tf(v.y), f2tf(v.z), f2tf(v.w));
        *(uint4*)(Xs + n * XS_STRIDE + (c4 << 2)) = u;
    }

    const float* Wm[3] = {Wq, Wk, Wv};
    const float* Bm[3] = {bq, bk, bv};
    float*       Gm[3] = {g_q, g_k, g_v};

#pragma unroll
    for (int m = 0; m < 3; ++m) {
        float acc[2][8][4];
#pragma unroll
        for (int mt = 0; mt < 2; ++mt)
#pragma unroll
            for (int nt = 0; nt < 8; ++nt)
#pragma unroll
                for (int q = 0; q < 4; ++q) acc[mt][nt][q] = 0.0f;

        const float* W = Wm[m];
        for (int kc = 0; kc < 8; ++kc) {     // K chunks of 32
            __syncthreads();
#pragma unroll
            for (int it = 0; it < 8; ++it) {
                int idx = tid + it * 256;    // float4 index 0..2047
                int kk  = idx >> 6;
                int c4  = idx & 63;
                float4 v = *(const float4*)(W + ((kc * 32 + kk) << 8) + (c4 << 2));
                uint4 u = make_uint4(f2tf(v.x), f2tf(v.y), f2tf(v.z), f2tf(v.w));
                *(uint4*)(Wt + kk * WT_STRIDE + (c4 << 2)) = u;
            }
            __syncthreads();
#pragma unroll
            for (int ks = 0; ks < 4; ++ks) { // k-steps of 8
                const int kb = ks * 8;
                unsigned a[2][4];
#pragma unroll
                for (int mt = 0; mt < 2; ++mt) {
                    const unsigned* ar = Xs + (mhalf * 32 + mt * 16 + g) * XS_STRIDE
                                            + kc * 32 + kb + t;
                    a[mt][0] = ar[0];
                    a[mt][1] = ar[8 * XS_STRIDE];
                    a[mt][2] = ar[4];
                    a[mt][3] = ar[8 * XS_STRIDE + 4];
                }
                unsigned bfr[8][2];
#pragma unroll
                for (int nt = 0; nt < 8; ++nt) {
                    const unsigned* br = Wt + (kb + t) * WT_STRIDE + nq * 64 + nt * 8 + g;
                    bfr[nt][0] = br[0];
                    bfr[nt][1] = br[4 * WT_STRIDE];
                }
#pragma unroll
                for (int mt = 0; mt < 2; ++mt)
#pragma unroll
                    for (int nt = 0; nt < 8; ++nt)
                        mma8(acc[mt][nt], a[mt], bfr[nt]);
            }
        }

        // bias
        float2 bb[8];
#pragma unroll
        for (int nt = 0; nt < 8; ++nt)
            bb[nt] = *(const float2*)(Bm[m] + nq * 64 + nt * 8 + 2 * t);
#pragma unroll
        for (int mt = 0; mt < 2; ++mt)
#pragma unroll
            for (int nt = 0; nt < 8; ++nt) {
                acc[mt][nt][0] += bb[nt].x;  acc[mt][nt][1] += bb[nt].y;
                acc[mt][nt][2] += bb[nt].x;  acc[mt][nt][3] += bb[nt].y;
            }

        // cosine normalization for q,k over each head's 32 dims
        // (one C row lives in 4 lanes sharing g -> shfl_xor 1,2)
        if (m < 2) {
#pragma unroll
            for (int mt = 0; mt < 2; ++mt)
#pragma unroll
                for (int rh = 0; rh < 2; ++rh)
#pragma unroll
                    for (int hh = 0; hh < 2; ++hh) {
                        float s = 0.0f;
#pragma unroll
                        for (int k2 = 0; k2 < 4; ++k2) {
                            int nt = hh * 4 + k2;
                            s += acc[mt][nt][rh * 2]     * acc[mt][nt][rh * 2]
                               + acc[mt][nt][rh * 2 + 1] * acc[mt][nt][rh * 2 + 1];
                        }
                        s += __shfl_xor_sync(0xffffffffu, s, 1);
                        s += __shfl_xor_sync(0xffffffffu, s, 2);
                        float inv = 1.0f / fmaxf(sqrtf(s), 1e-12f);
#pragma unroll
                        for (int k2 = 0; k2 < 4; ++k2) {
                            int nt = hh * 4 + k2;
                            acc[mt][nt][rh * 2]     *= inv;
                            acc[mt][nt][rh * 2 + 1] *= inv;
                        }
                    }
        }

        // store [win][head][tok][hd]
        float* G = Gm[m];
#pragma unroll
        for (int mt = 0; mt < 2; ++mt)
#pragma unroll
            for (int rh = 0; rh < 2; ++rh)
#pragma unroll
                for (int nt = 0; nt < 8; ++nt) {
                    int n    = mhalf * 32 + mt * 16 + rh * 8 + g;
                    int col  = nq * 64 + nt * 8 + 2 * t;
                    int head = col >> 5;
                    int d    = col & 31;
                    *(float2*)(G + (((w << 3) | head) << 11) + (n << 5) + d) =
                        make_float2(acc[mt][nt][rh * 2], acc[mt][nt][rh * 2 + 1]);
                }
    }
}

// ============================================================
// Kernel 2: per (window, head) attention.  grid (1024, 8), 64 threads.
// ============================================================
__global__ void __launch_bounds__(64)
swin_attn_kernel()
{
    __shared__ float ks[NTOK * HD];
    __shared__ float vs[NTOK * HD];
    __shared__ float ps[NTOK * 65];
    __shared__ float bs[225];

    const int w   = blockIdx.x;
    const int h   = blockIdx.y;
    const int tid = threadIdx.x;
    const int base = ((w << 3) | h) << 11;

    const float4* k4 = (const float4*)(g_k + base);
    const float4* v4 = (const float4*)(g_v + base);
#pragma unroll
    for (int it = 0; it < 8; ++it) {
        int idx = tid + it * 64;
        ((float4*)ks)[idx] = k4[idx];
        ((float4*)vs)[idx] = v4[idx];
    }
    for (int idx = tid; idx < 225; idx += 64) bs[idx] = g_bias16[h * 225 + idx];

    float qr[32];
    const float4* q4 = (const float4*)(g_q + base + tid * HD);
#pragma unroll
    for (int it = 0; it < 8; ++it) ((float4*)qr)[it] = q4[it];
    __syncthreads();

    const float sc = g_scale[h];
    const int wy = (w >> 3) & 7, wx = w & 7;
    const int ty = tid >> 3,     tx = tid & 7;
    const bool mh = (wy == 7), mw = (wx == 7);
    const bool tyl = (ty < 4), txl = (tx < 4);

    float mx = -1e30f;
    for (int m = 0; m < 64; ++m) {
        float dot = 0.0f;
#pragma unroll
        for (int d = 0; d < 32; ++d) dot += qr[d] * ks[m * 32 + d];
        int my = m >> 3, mxc = m & 7;
        float l = dot * sc + bs[(ty - my + 7) * 15 + (tx - mxc + 7)];
        if (mh && (tyl != (my < 4)))  l -= 100.0f;
        if (mw && (txl != (mxc < 4))) l -= 100.0f;
        ps[tid * 65 + m] = l;
        mx = fmaxf(mx, l);
    }

    float sum = 0.0f;
    for (int m = 0; m < 64; ++m) {
        float e = __expf(ps[tid * 65 + m] - mx);
        ps[tid * 65 + m] = e;
        sum += e;
    }
    const float inv = 1.0f / sum;

    float o[32];
#pragma unroll
    for (int d = 0; d < 32; ++d) o[d] = 0.0f;
    for (int m = 0; m < 64; ++m) {
        float p = ps[tid * 65 + m];
#pragma unroll
        for (int d = 0; d < 32; ++d) o[d] += p * vs[m * 32 + d];
    }

    float* dst = g_ao + ((w << 6) | tid) * CDIM + h * HD;
#pragma unroll
    for (int it = 0; it < 8; ++it)
        ((float4*)dst)[it] = make_float4(o[it * 4] * inv, o[it * 4 + 1] * inv,
                                         o[it * 4 + 2] * inv, o[it * 4 + 3] * inv);
}

// ============================================================
// Kernel 3: output projection (tf32 MMA) + inverse window/roll scatter
// ============================================================
__global__ void __launch_bounds__(256, 2)
swin_proj_kernel(const float* __restrict__ Wo, const float* __restrict__ bo,
                 float* __restrict__ out)
{
    extern __shared__ unsigned sm[];
    unsigned* Xs = sm;
    unsigned* Wt = sm + 64 * XS_STRIDE;

    const int w    = blockIdx.x;
    const int b    = w >> 6;
    const int wy   = (w >> 3) & 7;
    const int wx   = w & 7;
    const int tid  = threadIdx.x;
    const int warp = tid >> 5;
    const int lane = tid & 31;
    const int g    = lane >> 2;
    const int t    = lane & 3;
    const int mhalf = warp >> 2;
    const int nq    = warp & 3;

#pragma unroll
    for (int it = 0; it < 16; ++it) {
        int idx = tid + it * 256;
        int n   = idx >> 6;
        int c4  = idx & 63;
        float4 v = *(const float4*)(g_ao + (w << 14) + (n << 8) + (c4 << 2));
        uint4 u = make_uint4(f2tf(v.x), f2tf(v.y), f2tf(v.z), f2tf(v.w));
        *(uint4*)(Xs + n * XS_STRIDE + (c4 << 2)) = u;
    }

    float acc[2][8][4];
#pragma unroll
    for (int mt = 0; mt < 2; ++mt)
#pragma unroll
        for (int nt = 0; nt < 8; ++nt)
#pragma unroll
            for (int q = 0; q < 4; ++q) acc[mt][nt][q] = 0.0f;

    for (int kc = 0; kc < 8; ++kc) {
        __syncthreads();
#pragma unroll
        for (int it = 0; it < 8; ++it) {
            int idx = tid + it * 256;
            int kk  = idx >> 6;
            int c4  = idx & 63;
            float4 v = *(const float4*)(Wo + ((kc * 32 + kk) << 8) + (c4 << 2));
            uint4 u = make_uint4(f2tf(v.x), f2tf(v.y), f2tf(v.z), f2tf(v.w));
            *(uint4*)(Wt + kk * WT_STRIDE + (c4 << 2)) = u;
        }
        __syncthreads();
#pragma unroll
        for (int ks = 0; ks < 4; ++ks) {
            const int kb = ks * 8;
            unsigned a[2][4];
#pragma unroll
            for (int mt = 0; mt < 2; ++mt) {
                const unsigned* ar = Xs + (mhalf * 32 + mt * 16 + g) * XS_STRIDE
                                        + kc * 32 + kb + t;
                a[mt][0] = ar[0];
                a[mt][1] = ar[8 * XS_STRIDE];
                a[mt][2] = ar[4];
                a[mt][3] = ar[8 * XS_STRIDE + 4];
            }
            unsigned bfr[8][2];
#pragma unroll
            for (int nt = 0; nt < 8; ++nt) {
                const unsigned* br = Wt + (kb + t) * WT_STRIDE + nq * 64 + nt * 8 + g;
                bfr[nt][0] = br[0];
                bfr[nt][1] = br[4 * WT_STRIDE];
            }
#pragma unroll
            for (int mt = 0; mt < 2; ++mt)
#pragma unroll
                for (int nt = 0; nt < 8; ++nt)
                    mma8(acc[mt][nt], a[mt], bfr[nt]);
        }
    }

    float2 bb[8];
#pragma unroll
    for (int nt = 0; nt < 8; ++nt)
        bb[nt] = *(const float2*)(bo + nq * 64 + nt * 8 + 2 * t);

#pragma unroll
    for (int mt = 0; mt < 2; ++mt)
#pragma unroll
        for (int rh = 0; rh < 2; ++rh)
#pragma unroll
            for (int nt = 0; nt < 8; ++nt) {
                int n   = mhalf * 32 + mt * 16 + rh * 8 + g;
                int ty  = n >> 3, tx = n & 7;
                int y   = ((wy << 3) + ty + 4) & 63;   // inverse roll
                int xc  = ((wx << 3) + tx + 4) & 63;
                int col = nq * 64 + nt * 8 + 2 * t;
                *(float2*)(out + (((b << 6) | y) << 14) + (xc << 8) + col) =
                    make_float2(acc[mt][nt][rh * 2] + bb[nt].x,
                                acc[mt][nt][rh * 2 + 1] + bb[nt].y);
            }
}

// ============================================================
extern "C" void kernel_launch(void* const* d_in, const int* in_sizes, int n_in,
                              void* d_out, int out_size)
{
    const float* x  = (const float*)d_in[0];
    const float* Wq = (const float*)d_in[1];
    const float* bq = (const float*)d_in[2];
    const float* Wk = (const float*)d_in[3];
    const float* bk = (const float*)d_in[4];
    const float* Wv = (const float*)d_in[5];
    const float* bv = (const float*)d_in[6];
    const float* Wo = (const float*)d_in[7];
    const float* bo = (const float*)d_in[8];
    const float* ls = (const float*)d_in[9];
    const float* w1 = (const float*)d_in[10];
    const float* b1 = (const float*)d_in[11];
    const float* w2 = (const float*)d_in[12];
    float* out = (float*)d_out;

    cudaFuncSetAttribute(swin_qkv_kernel,
                         cudaFuncAttributeMaxDynamicSharedMemorySize, GEMM_SMEM);
    cudaFuncSetAttribute(swin_proj_kernel,
                         cudaFuncAttributeMaxDynamicSharedMemorySize, GEMM_SMEM);

    swin_bias_kernel<<<225, 512>>>(ls, w1, b1, w2);
    swin_qkv_kernel<<<NWIN, 256, GEMM_SMEM>>>(x, Wq, bq, Wk, bk, Wv, bv);
    swin_attn_kernel<<<dim3(NWIN, NHEAD), 64>>>();
    swin_proj_kernel<<<NWIN, 256, GEMM_SMEM>>>(Wo, bo, out);
}